// round 4
// baseline (speedup 1.0000x reference)
#include <cuda_runtime.h>
#include <math.h>

#define BB 16
#define TT 12
#define NNODE 8600
#define HH 64
#define EE 128     // 2H
#define KK 66      // din_g = DIN + H
#define TM 32      // rows per block tile
#define ISTR 36    // padded sInp row stride (mult of 4 for float4, !=32 to break bank conflicts)

// ---------------- scratch (device globals: allowed) ----------------
__device__ float g_res[(long)BB * NNODE * EE];   // gate pre-activation "res" (70.4 MB)
__device__ float u_res[(long)BB * NNODE * HH];   // upd  pre-activation "res" (35.2 MB)
__device__ float g_agg[BB * EE];
__device__ float u_agg[BB * HH];

// ---------------- tiny per-step agg zeroing ----------------
__global__ void zero_agg_kernel() {
    int i = blockIdx.x * blockDim.x + threadIdx.x;
    if (i < BB * EE) g_agg[i] = 0.f;
    if (i < BB * HH) u_agg[i] = 0.f;
}

// ---------------- Kernel A: gate GEMMs + agg reduce ----------------
// inp = [x(2), state(64)] per row. Computes res = inp@Wa + (bias later),
// h = relu(inp@Wg + b) reduced over rows into g_agg[b][e].
// 256 threads: threads 0-127 -> Wa column e, threads 128-255 -> Wg column e.
extern "C" __global__ void __launch_bounds__(256, 2)
gate_mm_kernel(const float* __restrict__ x,
               const float* __restrict__ state_base, long bstride,
               const float* __restrict__ Wa, const float* __restrict__ ba,
               const float* __restrict__ Wg, const float* __restrict__ bg,
               int t)
{
    extern __shared__ float smem[];
    float* sW   = smem;                 // 2 * 66 * 128 = 16896 floats
    float* sb   = sW + 2 * KK * EE;     // 256 floats
    float* sInp = sb + 2 * EE;          // 66 * 36 = 2376 floats (16B-aligned offset)

    const int tid = threadIdx.x;
    const int b   = blockIdx.y;
    const int n0  = blockIdx.x * TM;

    for (int i = tid; i < KK * EE; i += 256) {
        sW[i]           = Wa[i];
        sW[KK * EE + i] = Wg[i];
    }
    if (tid < EE) { sb[tid] = ba[tid]; sb[EE + tid] = bg[tid]; }

    // x part (k = 0,1)
    for (int i = tid; i < TM * 2; i += 256) {
        int r = i >> 1, k = i & 1;
        int n = n0 + r;
        float v = 0.f;
        if (n < NNODE) v = x[(((long)b * TT + t) * NNODE + n) * 2 + k];
        sInp[k * ISTR + r] = v;
    }
    // state part (k = 2..65)
    for (int i = tid; i < TM * HH; i += 256) {
        int h = i & (HH - 1);
        int r = i >> 6;
        int n = n0 + r;
        float v = 0.f;
        if (n < NNODE) v = state_base[(long)b * bstride + (long)n * HH + h];
        sInp[(2 + h) * ISTR + r] = v;
    }
    __syncthreads();

    const int half = tid >> 7;         // 0: align (res), 1: gate (h)
    const int e    = tid & (EE - 1);
    const float* wcol = sW + half * (KK * EE) + e;

    float acc[TM];
    #pragma unroll
    for (int r = 0; r < TM; r++) acc[r] = 0.f;

    #pragma unroll 2
    for (int k = 0; k < KK; k++) {
        float w = wcol[k * EE];
        const float4* ip = (const float4*)(sInp + k * ISTR);
        #pragma unroll
        for (int rr = 0; rr < TM / 4; rr++) {
            float4 v = ip[rr];
            acc[rr * 4 + 0] += v.x * w;
            acc[rr * 4 + 1] += v.y * w;
            acc[rr * 4 + 2] += v.z * w;
            acc[rr * 4 + 3] += v.w * w;
        }
    }

    float bias = sb[half * EE + e];
    if (half == 0) {
        #pragma unroll
        for (int r = 0; r < TM; r++) {
            int n = n0 + r;
            if (n < NNODE) g_res[((long)b * NNODE + n) * EE + e] = acc[r] + bias;
        }
    } else {
        int nmax = NNODE - n0;
        float s = 0.f;
        #pragma unroll
        for (int r = 0; r < TM; r++)
            if (r < nmax) s += fmaxf(acc[r] + bias, 0.f);
        atomicAdd(&g_agg[b * EE + e], s);
    }
}

// ---------------- Kernel B: gate combine(z) -> cand GEMMs + agg2 reduce ----------------
extern "C" __global__ void __launch_bounds__(128, 4)
upd_mm_kernel(const float* __restrict__ x,
              const float* __restrict__ state_base, long bstride,
              const float* __restrict__ g_aff_w, const float* __restrict__ g_aff_b,
              const float* __restrict__ g_node_w, const float* __restrict__ g_add_w,
              const float* __restrict__ Wa, const float* __restrict__ ba,
              const float* __restrict__ Wg, const float* __restrict__ bg,
              int t)
{
    __shared__ float sW[2 * KK * HH];          // 8448 floats
    __shared__ float sb[2 * HH];
    __shared__ __align__(16) float sInp[KK * ISTR];
    __shared__ float sagg[HH];
    __shared__ float sS[TM];

    const int tid = threadIdx.x;
    const int b   = blockIdx.y;
    const int n0  = blockIdx.x * TM;

    for (int i = tid; i < KK * HH; i += 128) {
        sW[i]           = Wa[i];
        sW[KK * HH + i] = Wg[i];
    }
    if (tid < HH) { sb[tid] = ba[tid]; sb[HH + tid] = bg[tid]; sagg[tid] = g_agg[b * EE + tid]; }
    if (tid < TM) {
        int n = n0 + tid;
        sS[tid] = (n < NNODE) ? g_add_w[n] * g_node_w[n] : 0.f;
    }
    for (int i = tid; i < TM * 2; i += 128) {
        int r = i >> 1, k = i & 1;
        int n = n0 + r;
        sInp[k * ISTR + r] = (n < NNODE) ? x[(((long)b * TT + t) * NNODE + n) * 2 + k] : 0.f;
    }
    __syncthreads();

    // cand state part: z * state
    for (int i = tid; i < TM * HH; i += 128) {
        int h = i & (HH - 1);
        int r = i >> 6;
        int n = n0 + r;
        float v = 0.f;
        if (n < NNODE) {
            long m = (long)b * NNODE + n;
            float pre = g_res[m * EE + h]
                      + g_aff_w[(long)n * EE + h] * (sS[r] * sagg[h])
                      + g_aff_b[(long)n * EE + h];
            float z = 1.f / (1.f + __expf(-pre));
            v = z * state_base[(long)b * bstride + (long)n * HH + h];
        }
        sInp[(2 + h) * ISTR + r] = v;
    }
    __syncthreads();

    const int half = tid >> 6;   // 0: upd_align (res2), 1: upd_w (h2)
    const int e    = tid & (HH - 1);
    const float* wcol = sW + half * (KK * HH) + e;

    float acc[TM];
    #pragma unroll
    for (int r = 0; r < TM; r++) acc[r] = 0.f;

    #pragma unroll 2
    for (int k = 0; k < KK; k++) {
        float w = wcol[k * HH];
        const float4* ip = (const float4*)(sInp + k * ISTR);
        #pragma unroll
        for (int rr = 0; rr < TM / 4; rr++) {
            float4 v = ip[rr];
            acc[rr * 4 + 0] += v.x * w;
            acc[rr * 4 + 1] += v.y * w;
            acc[rr * 4 + 2] += v.z * w;
            acc[rr * 4 + 3] += v.w * w;
        }
    }

    float bias = sb[half * HH + e];
    if (half == 0) {
        #pragma unroll
        for (int r = 0; r < TM; r++) {
            int n = n0 + r;
            if (n < NNODE) u_res[((long)b * NNODE + n) * HH + e] = acc[r] + bias;
        }
    } else {
        int nmax = NNODE - n0;
        float s = 0.f;
        #pragma unroll
        for (int r = 0; r < TM; r++)
            if (r < nmax) s += fmaxf(acc[r] + bias, 0.f);
        atomicAdd(&u_agg[b * HH + e], s);
    }
}

// ---------------- Kernel C: final combine + output write ----------------
extern "C" __global__ void
combine_kernel(const float* __restrict__ state_base, long bstride,
               const float* __restrict__ g_aff_w, const float* __restrict__ g_aff_b,
               const float* __restrict__ g_node_w, const float* __restrict__ g_add_w,
               const float* __restrict__ u_aff_w, const float* __restrict__ u_aff_b,
               const float* __restrict__ u_node_w, const float* __restrict__ u_add_w,
               float* __restrict__ out, int t)
{
    long idx = (long)blockIdx.x * blockDim.x + threadIdx.x;
    const long total = (long)BB * NNODE * HH;
    if (idx >= total) return;

    int  h = (int)(idx & (HH - 1));
    long m = idx >> 6;                 // b*N + n
    int  b = (int)(m / NNODE);
    int  n = (int)(m - (long)b * NNODE);

    float sg = g_add_w[n] * g_node_w[n];
    float su = u_add_w[n] * u_node_w[n];

    // r = sigmoid of second half of gate output
    float rpre = g_res[m * EE + HH + h]
               + g_aff_w[(long)n * EE + HH + h] * (sg * g_agg[b * EE + HH + h])
               + g_aff_b[(long)n * EE + HH + h];
    float r = 1.f / (1.f + __expf(-rpre));

    float hcpre = u_res[m * HH + h]
                + u_aff_w[(long)n * HH + h] * (su * u_agg[b * HH + h])
                + u_aff_b[(long)n * HH + h];
    float hc = tanhf(hcpre);

    float st = state_base[(long)b * bstride + (long)n * HH + h];
    float hn = r * st + (1.f - r) * hc;

    out[(((long)b * TT + t) * NNODE + n) * HH + h] = hn;
    if (t == TT - 1)
        out[(long)BB * TT * NNODE * HH + m * HH + h] = hn;   // "last"
}

// ---------------- launch ----------------
extern "C" void kernel_launch(void* const* d_in, const int* in_sizes, int n_in,
                              void* d_out, int out_size)
{
    const float* x            = (const float*)d_in[0];
    const float* init_state   = (const float*)d_in[1];
    // d_in[2] node_emb0, d_in[3] node_emb1: unused by reference
    const float* gate_align_w = (const float*)d_in[4];
    const float* gate_align_b = (const float*)d_in[5];
    const float* gate_w       = (const float*)d_in[6];
    const float* gate_b       = (const float*)d_in[7];
    const float* gate_node_w  = (const float*)d_in[8];
    const float* gate_add_w   = (const float*)d_in[9];
    const float* gate_aff_w   = (const float*)d_in[10];
    const float* gate_aff_b   = (const float*)d_in[11];
    const float* upd_align_w  = (const float*)d_in[12];
    const float* upd_align_b  = (const float*)d_in[13];
    const float* upd_w        = (const float*)d_in[14];
    const float* upd_b        = (const float*)d_in[15];
    const float* upd_node_w   = (const float*)d_in[16];
    const float* upd_add_w    = (const float*)d_in[17];
    const float* upd_aff_w    = (const float*)d_in[18];
    const float* upd_aff_b    = (const float*)d_in[19];
    float* out = (float*)d_out;

    const int smemA = (2 * KK * EE + 2 * EE + KK * ISTR) * (int)sizeof(float); // 78,112 B
    // Attribute is persistent; first (non-captured) correctness call sets it.
    cudaFuncSetAttribute(gate_mm_kernel, cudaFuncAttributeMaxDynamicSharedMemorySize, smemA);

    dim3 gridMM((NNODE + TM - 1) / TM, BB);   // (269, 16)
    const long ctotal = (long)BB * NNODE * HH;
    const int  cgrid  = (int)((ctotal + 255) / 256);

    for (int t = 0; t < TT; t++) {
        const float* sb_ = (t == 0) ? init_state : (out + (long)(t - 1) * NNODE * HH);
        long bstride     = (t == 0) ? (long)NNODE * HH : (long)TT * NNODE * HH;

        zero_agg_kernel<<<(BB * EE + 255) / 256, 256>>>();

        gate_mm_kernel<<<gridMM, 256, smemA>>>(x, sb_, bstride,
                                               gate_align_w, gate_align_b,
                                               gate_w, gate_b, t);

        upd_mm_kernel<<<gridMM, 128>>>(x, sb_, bstride,
                                       gate_aff_w, gate_aff_b, gate_node_w, gate_add_w,
                                       upd_align_w, upd_align_b, upd_w, upd_b, t);

        combine_kernel<<<cgrid, 256>>>(sb_, bstride,
                                       gate_aff_w, gate_aff_b, gate_node_w, gate_add_w,
                                       upd_aff_w, upd_aff_b, upd_node_w, upd_add_w,
                                       out, t);
    }
}

// round 5
// speedup vs baseline: 1.0850x; 1.0850x over previous
#include <cuda_runtime.h>
#include <math.h>

#define BB 16
#define TT 12
#define NNODE 8600
#define HH 64
#define EE 128     // 2H
#define KK 66      // din_g = DIN + H
#define TM 32      // rows per block tile
#define ISTR 36    // padded sInp row stride (mult of 4 for 16B loads, !=32 to break conflicts)

// packed dual-fp32 FMA (Blackwell f32x2) — bitwise identical to 2x FFMA
#define FFMA2(acc, a, b) asm("fma.rn.f32x2 %0, %1, %2, %0;" : "+l"(acc) : "l"(a), "l"(b))

__device__ __forceinline__ unsigned long long pack2(float lo, float hi) {
    unsigned long long r;
    asm("mov.b64 %0, {%1, %2};" : "=l"(r) : "r"(__float_as_uint(lo)), "r"(__float_as_uint(hi)));
    return r;
}
__device__ __forceinline__ float lo32(unsigned long long v) {
    return __uint_as_float((unsigned)(v & 0xffffffffull));
}
__device__ __forceinline__ float hi32(unsigned long long v) {
    return __uint_as_float((unsigned)(v >> 32));
}

// ---------------- scratch (device globals: allowed) ----------------
__device__ float g_res[(long)BB * NNODE * EE];   // gate pre-activation "res" (70.4 MB)
__device__ float u_res[(long)BB * NNODE * HH];   // upd  pre-activation "res" (35.2 MB)
__device__ float g_agg[BB * EE];
__device__ float u_agg[BB * HH];

// ---------------- tiny per-step agg zeroing ----------------
__global__ void zero_agg_kernel() {
    int i = blockIdx.x * blockDim.x + threadIdx.x;
    if (i < BB * EE) g_agg[i] = 0.f;
    if (i < BB * HH) u_agg[i] = 0.f;
}

// ---------------- Kernel A: gate GEMMs + agg reduce ----------------
// inp = [x(2), state(64)] per row. Computes res = inp@Wa + bias,
// h = relu(inp@Wg + b) reduced over rows into g_agg[b][e].
// 256 threads: threads 0-127 -> Wa column e, threads 128-255 -> Wg column e.
extern "C" __global__ void __launch_bounds__(256, 2)
gate_mm_kernel(const float* __restrict__ x,
               const float* __restrict__ state_base, long bstride,
               const float* __restrict__ Wa, const float* __restrict__ ba,
               const float* __restrict__ Wg, const float* __restrict__ bg,
               int t)
{
    extern __shared__ float smem[];
    float* sW   = smem;                 // 2 * 66 * 128 = 16896 floats
    float* sb   = sW + 2 * KK * EE;     // 256 floats
    float* sInp = sb + 2 * EE;          // 66 * 36 floats (16B aligned: offset 17152 floats)

    const int tid = threadIdx.x;
    const int b   = blockIdx.y;
    const int n0  = blockIdx.x * TM;

    // vectorized weight staging (KK*EE = 8448 = 2112 float4s per matrix)
    {
        const float4* Wa4 = (const float4*)Wa;
        const float4* Wg4 = (const float4*)Wg;
        float4* sW4 = (float4*)sW;
        for (int i = tid; i < KK * EE / 4; i += 256) {
            sW4[i]                = Wa4[i];
            sW4[KK * EE / 4 + i]  = Wg4[i];
        }
    }
    if (tid < EE) { sb[tid] = ba[tid]; sb[EE + tid] = bg[tid]; }

    // x part (k = 0,1)
    for (int i = tid; i < TM * 2; i += 256) {
        int r = i >> 1, k = i & 1;
        int n = n0 + r;
        float v = 0.f;
        if (n < NNODE) v = x[(((long)b * TT + t) * NNODE + n) * 2 + k];
        sInp[k * ISTR + r] = v;
    }
    // state part (k = 2..65)
    for (int i = tid; i < TM * HH; i += 256) {
        int h = i & (HH - 1);
        int r = i >> 6;
        int n = n0 + r;
        float v = 0.f;
        if (n < NNODE) v = state_base[(long)b * bstride + (long)n * HH + h];
        sInp[(2 + h) * ISTR + r] = v;
    }
    __syncthreads();

    const int half = tid >> 7;         // 0: align (res), 1: gate (h)
    const int e    = tid & (EE - 1);
    const float* wcol = sW + half * (KK * EE) + e;

    unsigned long long acc[TM / 2];
    #pragma unroll
    for (int r = 0; r < TM / 2; r++) acc[r] = 0ull;

    #pragma unroll 2
    for (int k = 0; k < KK; k++) {
        float w = wcol[k * EE];
        unsigned long long ww = pack2(w, w);
        const ulonglong2* ip = (const ulonglong2*)(sInp + k * ISTR);
        #pragma unroll
        for (int rr = 0; rr < TM / 4; rr++) {
            ulonglong2 v = ip[rr];
            FFMA2(acc[rr * 2 + 0], v.x, ww);
            FFMA2(acc[rr * 2 + 1], v.y, ww);
        }
    }

    float bias = sb[half * EE + e];
    if (half == 0) {
        #pragma unroll
        for (int j = 0; j < TM / 2; j++) {
            int n = n0 + 2 * j;
            if (n < NNODE)     g_res[((long)b * NNODE + n)     * EE + e] = lo32(acc[j]) + bias;
            if (n + 1 < NNODE) g_res[((long)b * NNODE + n + 1) * EE + e] = hi32(acc[j]) + bias;
        }
    } else {
        int nmax = NNODE - n0;
        float s = 0.f;
        #pragma unroll
        for (int j = 0; j < TM / 2; j++) {
            if (2 * j     < nmax) s += fmaxf(lo32(acc[j]) + bias, 0.f);
            if (2 * j + 1 < nmax) s += fmaxf(hi32(acc[j]) + bias, 0.f);
        }
        atomicAdd(&g_agg[b * EE + e], s);
    }
}

// ---------------- Kernel B: gate combine(z) -> cand GEMMs + agg2 reduce ----------------
extern "C" __global__ void __launch_bounds__(128, 4)
upd_mm_kernel(const float* __restrict__ x,
              const float* __restrict__ state_base, long bstride,
              const float* __restrict__ g_aff_w, const float* __restrict__ g_aff_b,
              const float* __restrict__ g_node_w, const float* __restrict__ g_add_w,
              const float* __restrict__ Wa, const float* __restrict__ ba,
              const float* __restrict__ Wg, const float* __restrict__ bg,
              int t)
{
    __shared__ float sW[2 * KK * HH];          // 8448 floats
    __shared__ float sb[2 * HH];
    __shared__ __align__(16) float sInp[KK * ISTR];
    __shared__ float sagg[HH];
    __shared__ float sS[TM];

    const int tid = threadIdx.x;
    const int b   = blockIdx.y;
    const int n0  = blockIdx.x * TM;

    {
        const float4* Wa4 = (const float4*)Wa;
        const float4* Wg4 = (const float4*)Wg;
        float4* sW4 = (float4*)sW;
        for (int i = tid; i < KK * HH / 4; i += 128) {
            sW4[i]               = Wa4[i];
            sW4[KK * HH / 4 + i] = Wg4[i];
        }
    }
    if (tid < HH) { sb[tid] = ba[tid]; sb[HH + tid] = bg[tid]; sagg[tid] = g_agg[b * EE + tid]; }
    if (tid >= HH && tid < HH + TM) {
        int r = tid - HH;
        int n = n0 + r;
        sS[r] = (n < NNODE) ? g_add_w[n] * g_node_w[n] : 0.f;
    }
    for (int i = tid; i < TM * 2; i += 128) {
        int r = i >> 1, k = i & 1;
        int n = n0 + r;
        sInp[k * ISTR + r] = (n < NNODE) ? x[(((long)b * TT + t) * NNODE + n) * 2 + k] : 0.f;
    }
    __syncthreads();

    // cand state part: z * state
    for (int i = tid; i < TM * HH; i += 128) {
        int h = i & (HH - 1);
        int r = i >> 6;
        int n = n0 + r;
        float v = 0.f;
        if (n < NNODE) {
            long m = (long)b * NNODE + n;
            float pre = g_res[m * EE + h]
                      + g_aff_w[(long)n * EE + h] * (sS[r] * sagg[h])
                      + g_aff_b[(long)n * EE + h];
            float z = 1.f / (1.f + __expf(-pre));
            v = z * state_base[(long)b * bstride + (long)n * HH + h];
        }
        sInp[(2 + h) * ISTR + r] = v;
    }
    __syncthreads();

    const int half = tid >> 6;   // 0: upd_align (res2), 1: upd_w (h2)
    const int e    = tid & (HH - 1);
    const float* wcol = sW + half * (KK * HH) + e;

    unsigned long long acc[TM / 2];
    #pragma unroll
    for (int r = 0; r < TM / 2; r++) acc[r] = 0ull;

    #pragma unroll 2
    for (int k = 0; k < KK; k++) {
        float w = wcol[k * HH];
        unsigned long long ww = pack2(w, w);
        const ulonglong2* ip = (const ulonglong2*)(sInp + k * ISTR);
        #pragma unroll
        for (int rr = 0; rr < TM / 4; rr++) {
            ulonglong2 v = ip[rr];
            FFMA2(acc[rr * 2 + 0], v.x, ww);
            FFMA2(acc[rr * 2 + 1], v.y, ww);
        }
    }

    float bias = sb[half * HH + e];
    if (half == 0) {
        #pragma unroll
        for (int j = 0; j < TM / 2; j++) {
            int n = n0 + 2 * j;
            if (n < NNODE)     u_res[((long)b * NNODE + n)     * HH + e] = lo32(acc[j]) + bias;
            if (n + 1 < NNODE) u_res[((long)b * NNODE + n + 1) * HH + e] = hi32(acc[j]) + bias;
        }
    } else {
        int nmax = NNODE - n0;
        float s = 0.f;
        #pragma unroll
        for (int j = 0; j < TM / 2; j++) {
            if (2 * j     < nmax) s += fmaxf(lo32(acc[j]) + bias, 0.f);
            if (2 * j + 1 < nmax) s += fmaxf(hi32(acc[j]) + bias, 0.f);
        }
        atomicAdd(&u_agg[b * HH + e], s);
    }
}

// ---------------- Kernel C: final combine + output write (4 h per thread) ----------------
extern "C" __global__ void __launch_bounds__(256)
combine_kernel(const float* __restrict__ state_base, long bstride,
               const float* __restrict__ g_aff_w, const float* __restrict__ g_aff_b,
               const float* __restrict__ g_node_w, const float* __restrict__ g_add_w,
               const float* __restrict__ u_aff_w, const float* __restrict__ u_aff_b,
               const float* __restrict__ u_node_w, const float* __restrict__ u_add_w,
               float* __restrict__ out, int t)
{
    int i = blockIdx.x * 256 + threadIdx.x;          // i in [0, N * H/4)
    if (i >= NNODE * (HH / 4)) return;
    const int b = blockIdx.y;
    const int n = i >> 4;                            // H/4 = 16
    const int h = (i & 15) * 4;

    const long m = (long)b * NNODE + n;

    float sg = g_add_w[n] * g_node_w[n];
    float su = u_add_w[n] * u_node_w[n];

    float4 gr  = *(const float4*)(g_res   + m * EE + HH + h);
    float4 gaw = *(const float4*)(g_aff_w + (long)n * EE + HH + h);
    float4 gab = *(const float4*)(g_aff_b + (long)n * EE + HH + h);
    float4 gag = *(const float4*)(g_agg   + b * EE + HH + h);

    float4 ur  = *(const float4*)(u_res   + m * HH + h);
    float4 uaw = *(const float4*)(u_aff_w + (long)n * HH + h);
    float4 uab = *(const float4*)(u_aff_b + (long)n * HH + h);
    float4 uag = *(const float4*)(u_agg   + b * HH + h);

    float4 st  = *(const float4*)(state_base + (long)b * bstride + (long)n * HH + h);

    float4 hn;
    {
        float rp, r, hcp, hc;
        rp = gr.x + gaw.x * (sg * gag.x) + gab.x; r = 1.f / (1.f + __expf(-rp));
        hcp = ur.x + uaw.x * (su * uag.x) + uab.x; hc = tanhf(hcp);
        hn.x = r * st.x + (1.f - r) * hc;
        rp = gr.y + gaw.y * (sg * gag.y) + gab.y; r = 1.f / (1.f + __expf(-rp));
        hcp = ur.y + uaw.y * (su * uag.y) + uab.y; hc = tanhf(hcp);
        hn.y = r * st.y + (1.f - r) * hc;
        rp = gr.z + gaw.z * (sg * gag.z) + gab.z; r = 1.f / (1.f + __expf(-rp));
        hcp = ur.z + uaw.z * (su * uag.z) + uab.z; hc = tanhf(hcp);
        hn.z = r * st.z + (1.f - r) * hc;
        rp = gr.w + gaw.w * (sg * gag.w) + gab.w; r = 1.f / (1.f + __expf(-rp));
        hcp = ur.w + uaw.w * (su * uag.w) + uab.w; hc = tanhf(hcp);
        hn.w = r * st.w + (1.f - r) * hc;
    }

    *(float4*)(out + (((long)b * TT + t) * NNODE + n) * HH + h) = hn;
    if (t == TT - 1)
        *(float4*)(out + (long)BB * TT * NNODE * HH + m * HH + h) = hn;   // "last"
}

// ---------------- launch ----------------
extern "C" void kernel_launch(void* const* d_in, const int* in_sizes, int n_in,
                              void* d_out, int out_size)
{
    const float* x            = (const float*)d_in[0];
    const float* init_state   = (const float*)d_in[1];
    // d_in[2] node_emb0, d_in[3] node_emb1: unused by reference
    const float* gate_align_w = (const float*)d_in[4];
    const float* gate_align_b = (const float*)d_in[5];
    const float* gate_w       = (const float*)d_in[6];
    const float* gate_b       = (const float*)d_in[7];
    const float* gate_node_w  = (const float*)d_in[8];
    const float* gate_add_w   = (const float*)d_in[9];
    const float* gate_aff_w   = (const float*)d_in[10];
    const float* gate_aff_b   = (const float*)d_in[11];
    const float* upd_align_w  = (const float*)d_in[12];
    const float* upd_align_b  = (const float*)d_in[13];
    const float* upd_w        = (const float*)d_in[14];
    const float* upd_b        = (const float*)d_in[15];
    const float* upd_node_w   = (const float*)d_in[16];
    const float* upd_add_w    = (const float*)d_in[17];
    const float* upd_aff_w    = (const float*)d_in[18];
    const float* upd_aff_b    = (const float*)d_in[19];
    float* out = (float*)d_out;

    const int smemA = (2 * KK * EE + 2 * EE + KK * ISTR) * (int)sizeof(float); // 78,112 B
    cudaFuncSetAttribute(gate_mm_kernel, cudaFuncAttributeMaxDynamicSharedMemorySize, smemA);

    dim3 gridMM((NNODE + TM - 1) / TM, BB);                       // (269, 16)
    dim3 gridC((NNODE * (HH / 4) + 255) / 256, BB);               // (538, 16)

    for (int t = 0; t < TT; t++) {
        const float* sb_ = (t == 0) ? init_state : (out + (long)(t - 1) * NNODE * HH);
        long bstride     = (t == 0) ? (long)NNODE * HH : (long)TT * NNODE * HH;

        zero_agg_kernel<<<(BB * EE + 255) / 256, 256>>>();

        gate_mm_kernel<<<gridMM, 256, smemA>>>(x, sb_, bstride,
                                               gate_align_w, gate_align_b,
                                               gate_w, gate_b, t);

        upd_mm_kernel<<<gridMM, 128>>>(x, sb_, bstride,
                                       gate_aff_w, gate_aff_b, gate_node_w, gate_add_w,
                                       upd_align_w, upd_align_b, upd_w, upd_b, t);

        combine_kernel<<<gridC, 256>>>(sb_, bstride,
                                       gate_aff_w, gate_aff_b, gate_node_w, gate_add_w,
                                       upd_aff_w, upd_aff_b, upd_node_w, upd_add_w,
                                       out, t);
    }
}

// round 6
// speedup vs baseline: 1.1017x; 1.0154x over previous
#include <cuda_runtime.h>
#include <math.h>

#define BB 16
#define TT 12
#define NNODE 8600
#define HH 64
#define EE 128     // 2H
#define KK 66      // din_g = DIN + H
#define TM 32      // rows per block tile
#define ISTR 36    // padded sInp row stride (mult of 4 for 16B loads, !=32 to break conflicts)

// packed dual-fp32 FMA (Blackwell f32x2) — bitwise identical to 2x FFMA
#define FFMA2(acc, a, b) asm("fma.rn.f32x2 %0, %1, %2, %0;" : "+l"(acc) : "l"(a), "l"(b))

__device__ __forceinline__ unsigned long long pack2(float lo, float hi) {
    unsigned long long r;
    asm("mov.b64 %0, {%1, %2};" : "=l"(r) : "r"(__float_as_uint(lo)), "r"(__float_as_uint(hi)));
    return r;
}
__device__ __forceinline__ float lo32(unsigned long long v) {
    return __uint_as_float((unsigned)(v & 0xffffffffull));
}
__device__ __forceinline__ float hi32(unsigned long long v) {
    return __uint_as_float((unsigned)(v >> 32));
}

// ---------------- scratch (device globals: allowed) ----------------
__device__ float g_res[(long)BB * NNODE * EE];   // gate pre-activation "res" (70.4 MB)
__device__ float u_res[(long)BB * NNODE * HH];   // upd  pre-activation "res" (35.2 MB)
__device__ float g_agg[BB * EE];
__device__ float u_agg[BB * HH];

// ---------------- tiny per-step agg zeroing ----------------
__global__ void zero_agg_kernel() {
    int i = blockIdx.x * blockDim.x + threadIdx.x;
    if (i < BB * EE) g_agg[i] = 0.f;
    if (i < BB * HH) u_agg[i] = 0.f;
}

// ---------------- Kernel A: gate GEMMs + agg reduce ----------------
// inp = [x(2), state(64)] per row. Computes res = inp@Wa + bias,
// h = relu(inp@Wg + b) reduced over rows into g_agg[b][e].
// 256 threads: threads 0-127 -> Wa column e, threads 128-255 -> Wg column e.
extern "C" __global__ void __launch_bounds__(256, 2)
gate_mm_kernel(const float* __restrict__ x,
               const float* __restrict__ state_base, long bstride,
               const float* __restrict__ Wa, const float* __restrict__ ba,
               const float* __restrict__ Wg, const float* __restrict__ bg,
               int t)
{
    extern __shared__ float smem[];
    float* sW   = smem;                 // 2 * 66 * 128 = 16896 floats
    float* sb   = sW + 2 * KK * EE;     // 256 floats
    float* sInp = sb + 2 * EE;          // 66 * 36 floats (16B aligned: offset 17152 floats)

    const int tid = threadIdx.x;
    const int b   = blockIdx.y;
    const int n0  = blockIdx.x * TM;

    // vectorized weight staging (KK*EE = 8448 = 2112 float4s per matrix)
    {
        const float4* Wa4 = (const float4*)Wa;
        const float4* Wg4 = (const float4*)Wg;
        float4* sW4 = (float4*)sW;
        for (int i = tid; i < KK * EE / 4; i += 256) {
            sW4[i]                = Wa4[i];
            sW4[KK * EE / 4 + i]  = Wg4[i];
        }
    }
    if (tid < EE) { sb[tid] = ba[tid]; sb[EE + tid] = bg[tid]; }

    // x part (k = 0,1)
    for (int i = tid; i < TM * 2; i += 256) {
        int r = i >> 1, k = i & 1;
        int n = n0 + r;
        float v = 0.f;
        if (n < NNODE) v = x[(((long)b * TT + t) * NNODE + n) * 2 + k];
        sInp[k * ISTR + r] = v;
    }
    // state part (k = 2..65)
    for (int i = tid; i < TM * HH; i += 256) {
        int h = i & (HH - 1);
        int r = i >> 6;
        int n = n0 + r;
        float v = 0.f;
        if (n < NNODE) v = state_base[(long)b * bstride + (long)n * HH + h];
        sInp[(2 + h) * ISTR + r] = v;
    }
    __syncthreads();

    const int half = tid >> 7;         // 0: align (res), 1: gate (h)
    const int e    = tid & (EE - 1);
    const float* wcol = sW + half * (KK * EE) + e;

    unsigned long long acc[TM / 2];
    #pragma unroll
    for (int r = 0; r < TM / 2; r++) acc[r] = 0ull;

    #pragma unroll 2
    for (int k = 0; k < KK; k++) {
        float w = wcol[k * EE];
        unsigned long long ww = pack2(w, w);
        const ulonglong2* ip = (const ulonglong2*)(sInp + k * ISTR);
        #pragma unroll
        for (int rr = 0; rr < TM / 4; rr++) {
            ulonglong2 v = ip[rr];
            FFMA2(acc[rr * 2 + 0], v.x, ww);
            FFMA2(acc[rr * 2 + 1], v.y, ww);
        }
    }

    float bias = sb[half * EE + e];
    if (half == 0) {
        #pragma unroll
        for (int j = 0; j < TM / 2; j++) {
            int n = n0 + 2 * j;
            if (n < NNODE)     g_res[((long)b * NNODE + n)     * EE + e] = lo32(acc[j]) + bias;
            if (n + 1 < NNODE) g_res[((long)b * NNODE + n + 1) * EE + e] = hi32(acc[j]) + bias;
        }
    } else {
        int nmax = NNODE - n0;
        float s = 0.f;
        #pragma unroll
        for (int j = 0; j < TM / 2; j++) {
            if (2 * j     < nmax) s += fmaxf(lo32(acc[j]) + bias, 0.f);
            if (2 * j + 1 < nmax) s += fmaxf(hi32(acc[j]) + bias, 0.f);
        }
        atomicAdd(&g_agg[b * EE + e], s);
    }
}

// ---------------- Kernel B: gate combine(z) -> cand GEMMs + agg2 reduce ----------------
extern "C" __global__ void __launch_bounds__(128, 4)
upd_mm_kernel(const float* __restrict__ x,
              const float* __restrict__ state_base, long bstride,
              const float* __restrict__ g_aff_w, const float* __restrict__ g_aff_b,
              const float* __restrict__ g_node_w, const float* __restrict__ g_add_w,
              const float* __restrict__ Wa, const float* __restrict__ ba,
              const float* __restrict__ Wg, const float* __restrict__ bg,
              int t)
{
    __shared__ float sW[2 * KK * HH];          // 8448 floats
    __shared__ float sb[2 * HH];
    __shared__ __align__(16) float sInp[KK * ISTR];
    __shared__ float sagg[HH];
    __shared__ float sS[TM];

    const int tid = threadIdx.x;
    const int b   = blockIdx.y;
    const int n0  = blockIdx.x * TM;

    {
        const float4* Wa4 = (const float4*)Wa;
        const float4* Wg4 = (const float4*)Wg;
        float4* sW4 = (float4*)sW;
        for (int i = tid; i < KK * HH / 4; i += 128) {
            sW4[i]               = Wa4[i];
            sW4[KK * HH / 4 + i] = Wg4[i];
        }
    }
    if (tid < HH) { sb[tid] = ba[tid]; sb[HH + tid] = bg[tid]; sagg[tid] = g_agg[b * EE + tid]; }
    if (tid >= HH && tid < HH + TM) {
        int r = tid - HH;
        int n = n0 + r;
        sS[r] = (n < NNODE) ? g_add_w[n] * g_node_w[n] : 0.f;
    }
    for (int i = tid; i < TM * 2; i += 128) {
        int r = i >> 1, k = i & 1;
        int n = n0 + r;
        sInp[k * ISTR + r] = (n < NNODE) ? x[(((long)b * TT + t) * NNODE + n) * 2 + k] : 0.f;
    }
    __syncthreads();

    // cand state part: z * state
    for (int i = tid; i < TM * HH; i += 128) {
        int h = i & (HH - 1);
        int r = i >> 6;
        int n = n0 + r;
        float v = 0.f;
        if (n < NNODE) {
            long m = (long)b * NNODE + n;
            float pre = g_res[m * EE + h]
                      + g_aff_w[(long)n * EE + h] * (sS[r] * sagg[h])
                      + g_aff_b[(long)n * EE + h];
            float z = 1.f / (1.f + __expf(-pre));
            v = z * state_base[(long)b * bstride + (long)n * HH + h];
        }
        sInp[(2 + h) * ISTR + r] = v;
    }
    __syncthreads();

    const int half = tid >> 6;   // 0: upd_align (res2), 1: upd_w (h2)
    const int e    = tid & (HH - 1);
    const float* wcol = sW + half * (KK * HH) + e;

    unsigned long long acc[TM / 2];
    #pragma unroll
    for (int r = 0; r < TM / 2; r++) acc[r] = 0ull;

    #pragma unroll 2
    for (int k = 0; k < KK; k++) {
        float w = wcol[k * HH];
        unsigned long long ww = pack2(w, w);
        const ulonglong2* ip = (const ulonglong2*)(sInp + k * ISTR);
        #pragma unroll
        for (int rr = 0; rr < TM / 4; rr++) {
            ulonglong2 v = ip[rr];
            FFMA2(acc[rr * 2 + 0], v.x, ww);
            FFMA2(acc[rr * 2 + 1], v.y, ww);
        }
    }

    float bias = sb[half * HH + e];
    if (half == 0) {
        #pragma unroll
        for (int j = 0; j < TM / 2; j++) {
            int n = n0 + 2 * j;
            if (n < NNODE)     u_res[((long)b * NNODE + n)     * HH + e] = lo32(acc[j]) + bias;
            if (n + 1 < NNODE) u_res[((long)b * NNODE + n + 1) * HH + e] = hi32(acc[j]) + bias;
        }
    } else {
        int nmax = NNODE - n0;
        float s = 0.f;
        #pragma unroll
        for (int j = 0; j < TM / 2; j++) {
            if (2 * j     < nmax) s += fmaxf(lo32(acc[j]) + bias, 0.f);
            if (2 * j + 1 < nmax) s += fmaxf(hi32(acc[j]) + bias, 0.f);
        }
        atomicAdd(&u_agg[b * HH + e], s);
    }
}

// ---------------- Kernel C: final combine + output write (4 h per thread) ----------------
extern "C" __global__ void __launch_bounds__(256)
combine_kernel(const float* __restrict__ state_base, long bstride,
               const float* __restrict__ g_aff_w, const float* __restrict__ g_aff_b,
               const float* __restrict__ g_node_w, const float* __restrict__ g_add_w,
               const float* __restrict__ u_aff_w, const float* __restrict__ u_aff_b,
               const float* __restrict__ u_node_w, const float* __restrict__ u_add_w,
               float* __restrict__ out, int t)
{
    int i = blockIdx.x * 256 + threadIdx.x;          // i in [0, N * H/4)
    if (i >= NNODE * (HH / 4)) return;
    const int b = blockIdx.y;
    const int n = i >> 4;                            // H/4 = 16
    const int h = (i & 15) * 4;

    const long m = (long)b * NNODE + n;

    float sg = g_add_w[n] * g_node_w[n];
    float su = u_add_w[n] * u_node_w[n];

    float4 gr  = *(const float4*)(g_res   + m * EE + HH + h);
    float4 gaw = *(const float4*)(g_aff_w + (long)n * EE + HH + h);
    float4 gab = *(const float4*)(g_aff_b + (long)n * EE + HH + h);
    float4 gag = *(const float4*)(g_agg   + b * EE + HH + h);

    float4 ur  = *(const float4*)(u_res   + m * HH + h);
    float4 uaw = *(const float4*)(u_aff_w + (long)n * HH + h);
    float4 uab = *(const float4*)(u_aff_b + (long)n * HH + h);
    float4 uag = *(const float4*)(u_agg   + b * HH + h);

    float4 st  = *(const float4*)(state_base + (long)b * bstride + (long)n * HH + h);

    float4 hn;
    {
        float rp, r, hcp, hc;
        rp = gr.x + gaw.x * (sg * gag.x) + gab.x; r = 1.f / (1.f + __expf(-rp));
        hcp = ur.x + uaw.x * (su * uag.x) + uab.x; hc = tanhf(hcp);
        hn.x = r * st.x + (1.f - r) * hc;
        rp = gr.y + gaw.y * (sg * gag.y) + gab.y; r = 1.f / (1.f + __expf(-rp));
        hcp = ur.y + uaw.y * (su * uag.y) + uab.y; hc = tanhf(hcp);
        hn.y = r * st.y + (1.f - r) * hc;
        rp = gr.z + gaw.z * (sg * gag.z) + gab.z; r = 1.f / (1.f + __expf(-rp));
        hcp = ur.z + uaw.z * (su * uag.z) + uab.z; hc = tanhf(hcp);
        hn.z = r * st.z + (1.f - r) * hc;
        rp = gr.w + gaw.w * (sg * gag.w) + gab.w; r = 1.f / (1.f + __expf(-rp));
        hcp = ur.w + uaw.w * (su * uag.w) + uab.w; hc = tanhf(hcp);
        hn.w = r * st.w + (1.f - r) * hc;
    }

    *(float4*)(out + (((long)b * TT + t) * NNODE + n) * HH + h) = hn;
    if (t == TT - 1)
        *(float4*)(out + (long)BB * TT * NNODE * HH + m * HH + h) = hn;   // "last"
}

// ---------------- launch ----------------
extern "C" void kernel_launch(void* const* d_in, const int* in_sizes, int n_in,
                              void* d_out, int out_size)
{
    const float* x            = (const float*)d_in[0];
    const float* init_state   = (const float*)d_in[1];
    // d_in[2] node_emb0, d_in[3] node_emb1: unused by reference
    const float* gate_align_w = (const float*)d_in[4];
    const float* gate_align_b = (const float*)d_in[5];
    const float* gate_w       = (const float*)d_in[6];
    const float* gate_b       = (const float*)d_in[7];
    const float* gate_node_w  = (const float*)d_in[8];
    const float* gate_add_w   = (const float*)d_in[9];
    const float* gate_aff_w   = (const float*)d_in[10];
    const float* gate_aff_b   = (const float*)d_in[11];
    const float* upd_align_w  = (const float*)d_in[12];
    const float* upd_align_b  = (const float*)d_in[13];
    const float* upd_w        = (const float*)d_in[14];
    const float* upd_b        = (const float*)d_in[15];
    const float* upd_node_w   = (const float*)d_in[16];
    const float* upd_add_w    = (const float*)d_in[17];
    const float* upd_aff_w    = (const float*)d_in[18];
    const float* upd_aff_b    = (const float*)d_in[19];
    float* out = (float*)d_out;

    const int smemA = (2 * KK * EE + 2 * EE + KK * ISTR) * (int)sizeof(float); // 78,112 B
    cudaFuncSetAttribute(gate_mm_kernel, cudaFuncAttributeMaxDynamicSharedMemorySize, smemA);

    dim3 gridMM((NNODE + TM - 1) / TM, BB);                       // (269, 16)
    dim3 gridC((NNODE * (HH / 4) + 255) / 256, BB);               // (538, 16)

    for (int t = 0; t < TT; t++) {
        const float* sb_ = (t == 0) ? init_state : (out + (long)(t - 1) * NNODE * HH);
        long bstride     = (t == 0) ? (long)NNODE * HH : (long)TT * NNODE * HH;

        zero_agg_kernel<<<(BB * EE + 255) / 256, 256>>>();

        gate_mm_kernel<<<gridMM, 256, smemA>>>(x, sb_, bstride,
                                               gate_align_w, gate_align_b,
                                               gate_w, gate_b, t);

        upd_mm_kernel<<<gridMM, 128>>>(x, sb_, bstride,
                                       gate_aff_w, gate_aff_b, gate_node_w, gate_add_w,
                                       upd_align_w, upd_align_b, upd_w, upd_b, t);

        combine_kernel<<<gridC, 256>>>(sb_, bstride,
                                       gate_aff_w, gate_aff_b, gate_node_w, gate_add_w,
                                       upd_aff_w, upd_aff_b, upd_node_w, upd_add_w,
                                       out, t);
    }
}